// round 3
// baseline (speedup 1.0000x reference)
#include <cuda_runtime.h>

#define Nn   100000
#define Ee   1000000
#define FIN  128
#define HID  64
#define OUTF 40
#define NL   4
#define ALPHAc 0.5f
#define EPSBN  1e-5f

#define NB_SCAN ((Nn + 255) / 256)   // 391 blocks for histogram scan

// ---------------- scratch (static device globals) ---------------------------
__device__ __align__(16) float g_h0[Nn * HID];
__device__ __align__(16) float g_hprev[Nn * HID];
__device__ __align__(16) float g_support[Nn * HID];
__device__ __align__(16) float g_agg[Nn * HID];
__device__ float g_dinv[Nn];
__device__ float g_stats[2 * HID];
__device__ int   g_is64;
__device__ int   g_cnt[Nn];          // in-degree histogram
__device__ int   g_bsum[NB_SCAN];    // block sums
__device__ int   g_boff[NB_SCAN];    // block exclusive offsets
__device__ int   g_rowptr[Nn + 1];   // CSR pointers (by col)
__device__ int   g_cur[Nn];          // fill cursors
__device__ __align__(8) int2 g_eidx[Ee];  // {row*HID, w_bits}, col-sorted

// ---------------- edge index access (int32 vs int64 defensive) -------------
__device__ __forceinline__ int edge_at(const void* ei, int is64, int idx) {
    if (is64) return (int)((const long long*)ei)[idx];
    return ((const int*)ei)[idx];
}

__global__ void k_detect_zero(const void* ei) {
    int i = blockIdx.x * blockDim.x + threadIdx.x;
    if (i == 0) {
        const long long* p = (const long long*)ei;
        int ok = 1;
        for (int j = 0; j < 8; j++) {
            long long v = p[j];
            if (v < 0 || v >= Nn) ok = 0;
        }
        g_is64 = ok;
    }
    if (i < Nn) g_cnt[i] = 0;
}

__global__ void k_deg(const void* ei) {
    int e = blockIdx.x * blockDim.x + threadIdx.x;
    if (e < Ee) {
        int c = edge_at(ei, g_is64, Ee + e);
        atomicAdd(&g_cnt[c], 1);
    }
}

// block sums of g_cnt in chunks of 256
__global__ void k_bsum() {
    __shared__ int s[256];
    int t = threadIdx.x;
    int i = blockIdx.x * 256 + t;
    s[t] = (i < Nn) ? g_cnt[i] : 0;
    __syncthreads();
    for (int st = 128; st > 0; st >>= 1) {
        if (t < st) s[t] += s[t + st];
        __syncthreads();
    }
    if (t == 0) g_bsum[blockIdx.x] = s[0];
}

// exclusive scan of 391 block sums (single block, Hillis-Steele over 512)
__global__ void k_bscan() {
    __shared__ int s[512];
    int t = threadIdx.x;
    int orig = (t < NB_SCAN) ? g_bsum[t] : 0;
    s[t] = orig;
    __syncthreads();
    for (int off = 1; off < 512; off <<= 1) {
        int v = (t >= off) ? s[t - off] : 0;
        __syncthreads();
        s[t] += v;
        __syncthreads();
    }
    if (t < NB_SCAN) g_boff[t] = s[t] - orig;  // exclusive
}

// per-element exclusive scan within each 256-chunk + block offset -> rowptr
// also: dinv[i] = rsqrt(cnt+1), cur[i] = rowptr[i]
__global__ void k_rowptr() {
    __shared__ int s[256];
    int t = threadIdx.x;
    int i = blockIdx.x * 256 + t;
    int orig = (i < Nn) ? g_cnt[i] : 0;
    s[t] = orig;
    __syncthreads();
    for (int off = 1; off < 256; off <<= 1) {
        int v = (t >= off) ? s[t - off] : 0;
        __syncthreads();
        s[t] += v;
        __syncthreads();
    }
    if (i < Nn) {
        int rp = g_boff[blockIdx.x] + s[t] - orig;
        g_rowptr[i] = rp;
        g_cur[i] = rp;
        g_dinv[i] = rsqrtf((float)orig + 1.0f);
    }
    if (i == 0) g_rowptr[Nn] = Ee;
}

// fill CSR: col-sorted packed edges {row*HID, w}
__global__ void k_fill(const void* __restrict__ ei) {
    int e = blockIdx.x * blockDim.x + threadIdx.x;
    if (e < Ee) {
        int is64 = g_is64;
        int r = edge_at(ei, is64, e);
        int c = edge_at(ei, is64, Ee + e);
        float w = g_dinv[r] * g_dinv[c];
        int pos = atomicAdd(&g_cur[c], 1);
        g_eidx[pos] = make_int2(r * HID, __float_as_int(w));
    }
}

// ---------------- input GEMM: h = relu(x @ Wi + bi), 16-row tiles ----------
__global__ __launch_bounds__(256) void k_ingemm(const float* __restrict__ x,
                                                const float* __restrict__ Wi,
                                                const float* __restrict__ bi) {
    __shared__ float Ws[FIN * HID];   // 32 KB
    __shared__ float bs[HID];
    __shared__ float xs[16][FIN];     // 8 KB
    int tid = threadIdx.x;
    for (int i = tid; i < FIN * HID; i += 256) Ws[i] = Wi[i];
    if (tid < HID) bs[tid] = bi[tid];
    __syncthreads();
    int f = tid & 63, g = tid >> 6;
    const int ntiles = Nn / 16;  // 6250 exact
    for (int tile = blockIdx.x; tile < ntiles; tile += gridDim.x) {
        int rowBase = tile * 16;
        for (int i = tid; i < 16 * 32; i += 256) {
            int rr = i >> 5, q = (i & 31) * 4;
            *(float4*)(&xs[rr][q]) = *(const float4*)(x + (rowBase + rr) * FIN + q);
        }
        __syncthreads();
        float acc[4];
        #pragma unroll
        for (int i = 0; i < 4; i++) acc[i] = bs[f];
        #pragma unroll 4
        for (int k = 0; k < FIN; k++) {
            float wk = Ws[k * HID + f];
            #pragma unroll
            for (int i = 0; i < 4; i++)
                acc[i] = fmaf(xs[g * 4 + i][k], wk, acc[i]);
        }
        #pragma unroll
        for (int i = 0; i < 4; i++) {
            int gr = rowBase + g * 4 + i;
            float h = fmaxf(acc[i], 0.0f);
            g_h0[gr * HID + f] = h;
            g_hprev[gr * HID + f] = h;
        }
        __syncthreads();
    }
}

// ------- fused layer GEMM: support = hp + hp@W1 ; agg = a*h0 + h0@W2 --------
__global__ __launch_bounds__(256) void k_layergemm(const float* __restrict__ W1,
                                                   const float* __restrict__ W2) {
    __shared__ float W1s[HID * HID];
    __shared__ float W2s[HID * HID];
    __shared__ float hp[16][HID];
    __shared__ float h0s[16][HID];
    int tid = threadIdx.x;
    if (blockIdx.x == 0 && tid < 2 * HID) g_stats[tid] = 0.0f;
    for (int i = tid; i < HID * HID; i += 256) { W1s[i] = W1[i]; W2s[i] = W2[i]; }
    __syncthreads();
    int f = tid & 63, g = tid >> 6;
    const int ntiles = Nn / 16;
    for (int tile = blockIdx.x; tile < ntiles; tile += gridDim.x) {
        int rowBase = tile * 16;
        for (int i = tid; i < 16 * 16; i += 256) {
            int rr = i >> 4, q = (i & 15) * 4;
            *(float4*)(&hp[rr][q])  = *(const float4*)(g_hprev + (rowBase + rr) * HID + q);
            *(float4*)(&h0s[rr][q]) = *(const float4*)(g_h0    + (rowBase + rr) * HID + q);
        }
        __syncthreads();
        float a1[4], a2[4];
        #pragma unroll
        for (int i = 0; i < 4; i++) {
            int rr = g * 4 + i;
            a1[i] = hp[rr][f];
            a2[i] = ALPHAc * h0s[rr][f];
        }
        #pragma unroll 4
        for (int k = 0; k < HID; k++) {
            float w1k = W1s[k * HID + f];
            float w2k = W2s[k * HID + f];
            #pragma unroll
            for (int i = 0; i < 4; i++) {
                int rr = g * 4 + i;
                a1[i] = fmaf(hp[rr][k],  w1k, a1[i]);
                a2[i] = fmaf(h0s[rr][k], w2k, a2[i]);
            }
        }
        #pragma unroll
        for (int i = 0; i < 4; i++) {
            int gr = rowBase + g * 4 + i;
            g_support[gr * HID + f] = a1[i];
            g_agg[gr * HID + f]     = a2[i];
        }
        __syncthreads();
    }
}

// ---- CSR gather: agg[n] = initial + d^2*support[n] + sum_e w*support[row]
// ---- fused with BN stat accumulation. 16 threads per node.
__global__ __launch_bounds__(256) void k_gather() {
    __shared__ float4 s_sum[256];
    __shared__ float4 s_sq[256];
    int tid = threadIdx.x;
    int n = blockIdx.x * 16 + (tid >> 4);   // node
    int q = (tid & 15) * 4;                 // feature quad
    // initial + self loop
    float d = g_dinv[n];
    float sw = d * d;
    float4 acc = *(const float4*)(g_agg + n * HID + q);
    float4 s0  = *(const float4*)(g_support + n * HID + q);
    acc.x = fmaf(sw, s0.x, acc.x);
    acc.y = fmaf(sw, s0.y, acc.y);
    acc.z = fmaf(sw, s0.z, acc.z);
    acc.w = fmaf(sw, s0.w, acc.w);
    int p0 = g_rowptr[n], p1 = g_rowptr[n + 1];
    for (int p = p0; p < p1; p++) {
        int2 ed = __ldg(&g_eidx[p]);        // broadcast within 16-thread group
        float w = __int_as_float(ed.y);
        float4 s = __ldg((const float4*)(g_support + ed.x + q));
        acc.x = fmaf(w, s.x, acc.x);
        acc.y = fmaf(w, s.y, acc.y);
        acc.z = fmaf(w, s.z, acc.z);
        acc.w = fmaf(w, s.w, acc.w);
    }
    *(float4*)(g_agg + n * HID + q) = acc;
    // BN stats
    s_sum[tid] = acc;
    s_sq[tid] = make_float4(acc.x * acc.x, acc.y * acc.y, acc.z * acc.z, acc.w * acc.w);
    __syncthreads();
    for (int st = 128; st >= 16; st >>= 1) {
        if (tid < st) {
            float4 a = s_sum[tid], b = s_sum[tid + st];
            s_sum[tid] = make_float4(a.x + b.x, a.y + b.y, a.z + b.z, a.w + b.w);
            float4 c = s_sq[tid], e = s_sq[tid + st];
            s_sq[tid] = make_float4(c.x + e.x, c.y + e.y, c.z + e.z, c.w + e.w);
        }
        __syncthreads();
    }
    if (tid < 16) {
        float4 a = s_sum[tid], b = s_sq[tid];
        atomicAdd(&g_stats[tid * 4 + 0], a.x);
        atomicAdd(&g_stats[tid * 4 + 1], a.y);
        atomicAdd(&g_stats[tid * 4 + 2], a.z);
        atomicAdd(&g_stats[tid * 4 + 3], a.w);
        atomicAdd(&g_stats[HID + tid * 4 + 0], b.x);
        atomicAdd(&g_stats[HID + tid * 4 + 1], b.y);
        atomicAdd(&g_stats[HID + tid * 4 + 2], b.z);
        atomicAdd(&g_stats[HID + tid * 4 + 3], b.w);
    }
}

// hprev += relu(gamma*(y-m)*rsqrt(v+eps)+beta), float4
__global__ __launch_bounds__(256) void k_bnapply(const float* __restrict__ gamma,
                                                 const float* __restrict__ beta) {
    __shared__ float4 sc[16];
    __shared__ float4 sh[16];
    int tid = threadIdx.x;
    if (tid < HID) {
        float m = g_stats[tid] * (1.0f / Nn);
        float v = g_stats[HID + tid] * (1.0f / Nn) - m * m;
        float inv = rsqrtf(v + EPSBN);
        float scale = gamma[tid] * inv;
        ((float*)sc)[tid] = scale;
        ((float*)sh)[tid] = beta[tid] - m * scale;
    }
    __syncthreads();
    const int total4 = Nn * (HID / 4);
    for (int idx = blockIdx.x * 256 + tid; idx < total4; idx += gridDim.x * 256) {
        int fq = idx & 15;
        float4 s4 = sc[fq], h4 = sh[fq];
        float4 a = *(const float4*)(g_agg + idx * 4);
        float4 p = *(float4*)(g_hprev + idx * 4);
        p.x += fmaxf(fmaf(a.x, s4.x, h4.x), 0.f);
        p.y += fmaxf(fmaf(a.y, s4.y, h4.y), 0.f);
        p.z += fmaxf(fmaf(a.z, s4.z, h4.z), 0.f);
        p.w += fmaxf(fmaf(a.w, s4.w, h4.w), 0.f);
        *(float4*)(g_hprev + idx * 4) = p;
    }
}

// ---------------- output GEMM: out = hprev @ Wo + bo ------------------------
__global__ __launch_bounds__(256) void k_outgemm(const float* __restrict__ Wo,
                                                 const float* __restrict__ bo,
                                                 float* __restrict__ out) {
    __shared__ float Ws[HID * OUTF];
    __shared__ float bs[OUTF];
    __shared__ float hp[32][HID];
    int tid = threadIdx.x;
    for (int i = tid; i < HID * OUTF; i += 256) Ws[i] = Wo[i];
    if (tid < OUTF) bs[tid] = bo[tid];
    __syncthreads();
    int rowBase = blockIdx.x * 32;
    for (int i = tid; i < 32 * 16; i += 256) {
        int rr = i >> 4, q = (i & 15) * 4;
        int gr = rowBase + rr;
        float4 v = make_float4(0.f, 0.f, 0.f, 0.f);
        if (gr < Nn) v = *(const float4*)(g_hprev + gr * HID + q);
        *(float4*)(&hp[rr][q]) = v;
    }
    __syncthreads();
    for (int idx = tid; idx < 32 * OUTF; idx += 256) {
        int rr = idx / OUTF, f = idx % OUTF;
        int gr = rowBase + rr;
        if (gr >= Nn) continue;
        float acc = bs[f];
        #pragma unroll
        for (int k = 0; k < HID; k++) acc += hp[rr][k] * Ws[k * OUTF + f];
        out[gr * OUTF + f] = acc;
    }
}

// ---------------- launch ------------------------------------------------------
extern "C" void kernel_launch(void* const* d_in, const int* in_sizes, int n_in,
                              void* d_out, int out_size) {
    const float* x     = (const float*)d_in[0];
    const void*  ei    = d_in[1];
    const float* Wi    = (const float*)d_in[2];
    const float* bi    = (const float*)d_in[3];
    const float* w1    = (const float*)d_in[4];
    const float* w2    = (const float*)d_in[5];
    const float* gamma = (const float*)d_in[6];
    const float* beta  = (const float*)d_in[7];
    const float* Wo    = (const float*)d_in[8];
    const float* bo    = (const float*)d_in[9];
    float* out = (float*)d_out;

    // CSR build (col-sorted)
    k_detect_zero<<<(Nn + 255) / 256, 256>>>(ei);
    k_deg<<<(Ee + 255) / 256, 256>>>(ei);
    k_bsum<<<NB_SCAN, 256>>>();
    k_bscan<<<1, 512>>>();
    k_rowptr<<<NB_SCAN, 256>>>();
    k_fill<<<(Ee + 255) / 256, 256>>>(ei);

    k_ingemm<<<592, 256>>>(x, Wi, bi);

    for (int l = 0; l < NL; l++) {
        k_layergemm<<<592, 256>>>(w1 + l * HID * HID, w2 + l * HID * HID);
        k_gather<<<Nn / 16, 256>>>();
        k_bnapply<<<592, 256>>>(gamma + l * HID, beta + l * HID);
    }

    k_outgemm<<<(Nn + 31) / 32, 256>>>(Wo, bo, out);
}

// round 4
// speedup vs baseline: 1.4458x; 1.4458x over previous
#include <cuda_runtime.h>

#define Nn   100000
#define Ee   1000000
#define FIN  128
#define HID  64
#define OUTF 40
#define NL   4
#define ALPHAc 0.5f
#define EPSBN  1e-5f

#define NB_SCAN ((Nn + 255) / 256)   // 391

// ---------------- scratch ----------------------------------------------------
__device__ __align__(16) float g_h0[Nn * HID];
__device__ __align__(16) float g_hprev[Nn * HID];
__device__ __align__(16) float g_support[Nn * HID];
__device__ __align__(16) float g_agg[Nn * HID];
__device__ float g_dinv[Nn];
__device__ float g_stats[2][2 * HID];   // double-buffered by layer parity
__device__ int   g_is64;
__device__ int   g_cnt[Nn];
__device__ int   g_bsum[NB_SCAN];
__device__ int   g_boff[NB_SCAN];
__device__ int   g_rowptr[Nn + 1];
__device__ int   g_cur[Nn];
__device__ __align__(8) int2 g_eidx[Ee];  // {row*HID, w_bits}, col-sorted

// ---------------- edge index access ------------------------------------------
__device__ __forceinline__ int edge_at(const void* ei, int is64, int idx) {
    if (is64) return (int)((const long long*)ei)[idx];
    return ((const int*)ei)[idx];
}

__global__ void k_detect_zero(const void* ei) {
    int i = blockIdx.x * blockDim.x + threadIdx.x;
    if (i == 0) {
        const long long* p = (const long long*)ei;
        int ok = 1;
        for (int j = 0; j < 8; j++) {
            long long v = p[j];
            if (v < 0 || v >= Nn) ok = 0;
        }
        g_is64 = ok;
    }
    if (i < 4 * HID) ((float*)g_stats)[i] = 0.0f;
    if (i < Nn) g_cnt[i] = 0;
}

__global__ void k_deg(const void* ei) {
    int e = blockIdx.x * blockDim.x + threadIdx.x;
    if (e < Ee) {
        int c = edge_at(ei, g_is64, Ee + e);
        atomicAdd(&g_cnt[c], 1);
    }
}

__global__ void k_bsum() {
    __shared__ int s[256];
    int t = threadIdx.x;
    int i = blockIdx.x * 256 + t;
    s[t] = (i < Nn) ? g_cnt[i] : 0;
    __syncthreads();
    for (int st = 128; st > 0; st >>= 1) {
        if (t < st) s[t] += s[t + st];
        __syncthreads();
    }
    if (t == 0) g_bsum[blockIdx.x] = s[0];
}

__global__ void k_bscan() {
    __shared__ int s[512];
    int t = threadIdx.x;
    int orig = (t < NB_SCAN) ? g_bsum[t] : 0;
    s[t] = orig;
    __syncthreads();
    for (int off = 1; off < 512; off <<= 1) {
        int v = (t >= off) ? s[t - off] : 0;
        __syncthreads();
        s[t] += v;
        __syncthreads();
    }
    if (t < NB_SCAN) g_boff[t] = s[t] - orig;
}

__global__ void k_rowptr() {
    __shared__ int s[256];
    int t = threadIdx.x;
    int i = blockIdx.x * 256 + t;
    int orig = (i < Nn) ? g_cnt[i] : 0;
    s[t] = orig;
    __syncthreads();
    for (int off = 1; off < 256; off <<= 1) {
        int v = (t >= off) ? s[t - off] : 0;
        __syncthreads();
        s[t] += v;
        __syncthreads();
    }
    if (i < Nn) {
        int rp = g_boff[blockIdx.x] + s[t] - orig;
        g_rowptr[i] = rp;
        g_cur[i] = rp;
        g_dinv[i] = rsqrtf((float)orig + 1.0f);
    }
    if (i == 0) g_rowptr[Nn] = Ee;
}

__global__ void k_fill(const void* __restrict__ ei) {
    int e = blockIdx.x * blockDim.x + threadIdx.x;
    if (e < Ee) {
        int is64 = g_is64;
        int r = edge_at(ei, is64, e);
        int c = edge_at(ei, is64, Ee + e);
        float w = g_dinv[r] * g_dinv[c];
        int pos = atomicAdd(&g_cur[c], 1);
        g_eidx[pos] = make_int2(r * HID, __float_as_int(w));
    }
}

// ---------------- input GEMM -------------------------------------------------
__global__ __launch_bounds__(256) void k_ingemm(const float* __restrict__ x,
                                                const float* __restrict__ Wi,
                                                const float* __restrict__ bi) {
    __shared__ float Ws[FIN * HID];
    __shared__ float bs[HID];
    __shared__ float xs[16][FIN];
    int tid = threadIdx.x;
    for (int i = tid; i < FIN * HID; i += 256) Ws[i] = Wi[i];
    if (tid < HID) bs[tid] = bi[tid];
    __syncthreads();
    int f = tid & 63, g = tid >> 6;
    const int ntiles = Nn / 16;
    for (int tile = blockIdx.x; tile < ntiles; tile += gridDim.x) {
        int rowBase = tile * 16;
        for (int i = tid; i < 16 * 32; i += 256) {
            int rr = i >> 5, q = (i & 31) * 4;
            *(float4*)(&xs[rr][q]) = *(const float4*)(x + (rowBase + rr) * FIN + q);
        }
        __syncthreads();
        float acc[4];
        #pragma unroll
        for (int i = 0; i < 4; i++) acc[i] = bs[f];
        #pragma unroll 4
        for (int k = 0; k < FIN; k++) {
            float wk = Ws[k * HID + f];
            #pragma unroll
            for (int i = 0; i < 4; i++)
                acc[i] = fmaf(xs[g * 4 + i][k], wk, acc[i]);
        }
        #pragma unroll
        for (int i = 0; i < 4; i++) {
            int gr = rowBase + g * 4 + i;
            float h = fmaxf(acc[i], 0.0f);
            g_h0[gr * HID + f] = h;
            g_hprev[gr * HID + f] = h;
        }
        __syncthreads();
    }
}

// ------- layer GEMM with fused BN(prev layer)+ReLU+residual -----------------
// apply==0: hp tile = g_hprev.  apply==1: hnew = hprev + relu(agg*sc+sh),
// stored to g_hprev and used as GEMM input. Block 0 zeroes stats buffer zb.
__global__ __launch_bounds__(256) void k_layergemm(const float* __restrict__ W1,
                                                   const float* __restrict__ W2,
                                                   const float* __restrict__ gamma,
                                                   const float* __restrict__ beta,
                                                   int apply, int rb, int zb) {
    __shared__ float W1s[HID * HID];
    __shared__ float W2s[HID * HID];
    __shared__ float hp[16][HID];
    __shared__ float h0s[16][HID];
    int tid = threadIdx.x;
    if (blockIdx.x == 0 && tid < 2 * HID) g_stats[zb][tid] = 0.0f;
    for (int i = tid; i < HID * HID; i += 256) { W1s[i] = W1[i]; W2s[i] = W2[i]; }
    int f = tid & 63, g = tid >> 6;
    float sc = 0.f, sh = 0.f;
    if (apply) {
        float m = g_stats[rb][f] * (1.0f / Nn);
        float v = g_stats[rb][HID + f] * (1.0f / Nn) - m * m;
        float inv = rsqrtf(v + EPSBN);
        sc = gamma[f] * inv;
        sh = beta[f] - m * sc;
    }
    __syncthreads();
    const int ntiles = Nn / 16;
    for (int tile = blockIdx.x; tile < ntiles; tile += gridDim.x) {
        int rowBase = tile * 16;
        if (apply) {
            #pragma unroll
            for (int i = 0; i < 4; i++) {
                int gr = rowBase + g * 4 + i;
                float hv = g_hprev[gr * HID + f]
                         + fmaxf(fmaf(g_agg[gr * HID + f], sc, sh), 0.0f);
                hp[g * 4 + i][f] = hv;
                g_hprev[gr * HID + f] = hv;
            }
            for (int i = tid; i < 16 * 16; i += 256) {
                int rr = i >> 4, q = (i & 15) * 4;
                *(float4*)(&h0s[rr][q]) = *(const float4*)(g_h0 + (rowBase + rr) * HID + q);
            }
        } else {
            for (int i = tid; i < 16 * 16; i += 256) {
                int rr = i >> 4, q = (i & 15) * 4;
                *(float4*)(&hp[rr][q])  = *(const float4*)(g_hprev + (rowBase + rr) * HID + q);
                *(float4*)(&h0s[rr][q]) = *(const float4*)(g_h0    + (rowBase + rr) * HID + q);
            }
        }
        __syncthreads();
        float a1[4], a2[4];
        #pragma unroll
        for (int i = 0; i < 4; i++) {
            int rr = g * 4 + i;
            a1[i] = hp[rr][f];
            a2[i] = ALPHAc * h0s[rr][f];
        }
        #pragma unroll 4
        for (int k = 0; k < HID; k++) {
            float w1k = W1s[k * HID + f];
            float w2k = W2s[k * HID + f];
            #pragma unroll
            for (int i = 0; i < 4; i++) {
                int rr = g * 4 + i;
                a1[i] = fmaf(hp[rr][k],  w1k, a1[i]);
                a2[i] = fmaf(h0s[rr][k], w2k, a2[i]);
            }
        }
        #pragma unroll
        for (int i = 0; i < 4; i++) {
            int gr = rowBase + g * 4 + i;
            g_support[gr * HID + f] = a1[i];
            g_agg[gr * HID + f]     = a2[i];
        }
        __syncthreads();
    }
}

// ---- warp-per-node CSR gather + BN stats (grid-stride, reg-resident stats) --
__global__ __launch_bounds__(256) void k_gather(int wb) {
    __shared__ float4 s_sum[8][16];
    __shared__ float4 s_sq[8][16];
    int tid = threadIdx.x;
    int wid = tid >> 5;           // warp -> node
    int lane = tid & 31;
    int half = lane >> 4;         // which edge of the pair
    int q = (lane & 15) * 4;      // feature quad
    float4 lsum = make_float4(0.f, 0.f, 0.f, 0.f);
    float4 lsq  = make_float4(0.f, 0.f, 0.f, 0.f);
    const int nwarps = gridDim.x * 8;
    for (int n = blockIdx.x * 8 + wid; n < Nn; n += nwarps) {
        float4 acc = make_float4(0.f, 0.f, 0.f, 0.f);
        if (half == 0) {
            float d = g_dinv[n];
            float sw = d * d;
            float4 a  = *(const float4*)(g_agg + n * HID + q);
            float4 s0 = *(const float4*)(g_support + n * HID + q);
            acc.x = fmaf(sw, s0.x, a.x);
            acc.y = fmaf(sw, s0.y, a.y);
            acc.z = fmaf(sw, s0.z, a.z);
            acc.w = fmaf(sw, s0.w, a.w);
        }
        int p0 = g_rowptr[n], p1 = g_rowptr[n + 1];
        #pragma unroll 2
        for (int p = p0 + half; p < p1; p += 2) {
            int2 ed = __ldg(&g_eidx[p]);
            float w = __int_as_float(ed.y);
            float4 s = __ldg((const float4*)(g_support + ed.x + q));
            acc.x = fmaf(w, s.x, acc.x);
            acc.y = fmaf(w, s.y, acc.y);
            acc.z = fmaf(w, s.z, acc.z);
            acc.w = fmaf(w, s.w, acc.w);
        }
        // combine the two halves
        acc.x += __shfl_xor_sync(0xffffffffu, acc.x, 16);
        acc.y += __shfl_xor_sync(0xffffffffu, acc.y, 16);
        acc.z += __shfl_xor_sync(0xffffffffu, acc.z, 16);
        acc.w += __shfl_xor_sync(0xffffffffu, acc.w, 16);
        if (half == 0) {
            *(float4*)(g_agg + n * HID + q) = acc;
            lsum.x += acc.x; lsum.y += acc.y; lsum.z += acc.z; lsum.w += acc.w;
            lsq.x += acc.x * acc.x; lsq.y += acc.y * acc.y;
            lsq.z += acc.z * acc.z; lsq.w += acc.w * acc.w;
        }
    }
    if (half == 0) {
        s_sum[wid][lane & 15] = lsum;
        s_sq[wid][lane & 15]  = lsq;
    }
    __syncthreads();
    if (tid < 16) {
        float4 a = s_sum[0][tid], b = s_sq[0][tid];
        #pragma unroll
        for (int wv = 1; wv < 8; wv++) {
            float4 c = s_sum[wv][tid], d = s_sq[wv][tid];
            a.x += c.x; a.y += c.y; a.z += c.z; a.w += c.w;
            b.x += d.x; b.y += d.y; b.z += d.z; b.w += d.w;
        }
        float* st = g_stats[wb];
        atomicAdd(&st[tid * 4 + 0], a.x);
        atomicAdd(&st[tid * 4 + 1], a.y);
        atomicAdd(&st[tid * 4 + 2], a.z);
        atomicAdd(&st[tid * 4 + 3], a.w);
        atomicAdd(&st[HID + tid * 4 + 0], b.x);
        atomicAdd(&st[HID + tid * 4 + 1], b.y);
        atomicAdd(&st[HID + tid * 4 + 2], b.z);
        atomicAdd(&st[HID + tid * 4 + 3], b.w);
    }
}

// ---------------- output GEMM with fused final BN ---------------------------
__global__ __launch_bounds__(256) void k_outgemm(const float* __restrict__ Wo,
                                                 const float* __restrict__ bo,
                                                 const float* __restrict__ gamma,
                                                 const float* __restrict__ beta,
                                                 int rb,
                                                 float* __restrict__ out) {
    __shared__ float Ws[HID * OUTF];
    __shared__ float bs[OUTF];
    __shared__ float hp[32][HID];
    __shared__ float scs[HID];
    __shared__ float shs[HID];
    int tid = threadIdx.x;
    for (int i = tid; i < HID * OUTF; i += 256) Ws[i] = Wo[i];
    if (tid < OUTF) bs[tid] = bo[tid];
    if (tid < HID) {
        float m = g_stats[rb][tid] * (1.0f / Nn);
        float v = g_stats[rb][HID + tid] * (1.0f / Nn) - m * m;
        float inv = rsqrtf(v + EPSBN);
        float scale = gamma[tid] * inv;
        scs[tid] = scale;
        shs[tid] = beta[tid] - m * scale;
    }
    __syncthreads();
    int rowBase = blockIdx.x * 32;
    for (int i = tid; i < 32 * HID; i += 256) {
        int rr = i >> 6, f = i & 63;
        int gr = rowBase + rr;
        float hv = g_hprev[gr * HID + f]
                 + fmaxf(fmaf(g_agg[gr * HID + f], scs[f], shs[f]), 0.0f);
        hp[rr][f] = hv;
    }
    __syncthreads();
    for (int idx = tid; idx < 32 * OUTF; idx += 256) {
        int rr = idx / OUTF, f = idx % OUTF;
        int gr = rowBase + rr;
        float acc = bs[f];
        #pragma unroll
        for (int k = 0; k < HID; k++) acc += hp[rr][k] * Ws[k * OUTF + f];
        out[gr * OUTF + f] = acc;
    }
}

// ---------------- launch ------------------------------------------------------
extern "C" void kernel_launch(void* const* d_in, const int* in_sizes, int n_in,
                              void* d_out, int out_size) {
    const float* x     = (const float*)d_in[0];
    const void*  ei    = d_in[1];
    const float* Wi    = (const float*)d_in[2];
    const float* bi    = (const float*)d_in[3];
    const float* w1    = (const float*)d_in[4];
    const float* w2    = (const float*)d_in[5];
    const float* gamma = (const float*)d_in[6];
    const float* beta  = (const float*)d_in[7];
    const float* Wo    = (const float*)d_in[8];
    const float* bo    = (const float*)d_in[9];
    float* out = (float*)d_out;

    k_detect_zero<<<(Nn + 255) / 256, 256>>>(ei);
    k_deg<<<(Ee + 255) / 256, 256>>>(ei);
    k_bsum<<<NB_SCAN, 256>>>();
    k_bscan<<<1, 512>>>();
    k_rowptr<<<NB_SCAN, 256>>>();
    k_fill<<<(Ee + 255) / 256, 256>>>(ei);

    k_ingemm<<<592, 256>>>(x, Wi, bi);

    for (int l = 0; l < NL; l++) {
        int wb = l & 1;             // stats buffer gather(l) writes
        int rb = (l - 1) & 1;       // stats buffer layergemm reads (l>0)
        k_layergemm<<<592, 256>>>(w1 + l * HID * HID, w2 + l * HID * HID,
                                  gamma + (l - 1) * HID, beta + (l - 1) * HID,
                                  (l > 0) ? 1 : 0, rb, wb);
        k_gather<<<1184, 256>>>(wb);
    }

    k_outgemm<<<Nn / 32, 256>>>(Wo, bo, gamma + (NL - 1) * HID,
                                beta + (NL - 1) * HID, (NL - 1) & 1, out);
}